// round 12
// baseline (speedup 1.0000x reference)
#include <cuda_runtime.h>

#define BATCH 32
#define HW    16384          // 128*128
#define NPIX  (BATCH * HW)   // 524288
#define NMIXK 10
#define TPB   256
#define VEC   2
#define NBLK  (NPIX / (TPB * VEC))   // 1024

__device__ double       g_part[NBLK];
__device__ unsigned int g_count = 0;

// hardware tanh: 1 MUFU op, abs err ~5e-4
__device__ __forceinline__ float tanh_hw(float v) {
    float r;
    asm("tanh.approx.f32 %0, %1;" : "=f"(r) : "f"(v));
    return r;
}

__device__ __forceinline__ float2 ld2(const float* p) {
    return __ldg(reinterpret_cast<const float2*>(p));
}

// per-(channel, mixture) log-prob: 3 MUFU (EX2, EX2, LG2), edge cases inline
// (body frozen since R8).
__device__ __forceinline__ float chlp(float x, float mu, float lsr) {
    float ls  = fmaxf(lsr, -7.0f);
    float inv = __expf(-ls);                             // MUFU 1
    float mid = inv * (x - mu);
    float d   = inv * (1.0f / 255.0f);                   // half-width > 0
    float am  = fabsf(mid);
    float g   = __expf(-am);                             // MUFU 2

    float d2 = d * d;
    // polynomials valid for d <= 1 (typical d ~ 4e-3)
    float sh     = d * fmaf(d2, fmaf(d2, 8.3333333e-3f, 0.16666667f), 1.0f);
    float ch     = fmaf(d2, fmaf(d2, 4.1666667e-2f, 0.5f), 1.0f);
    float log_sc = d2 * fmaf(d2, -5.5555556e-3f, 0.16666667f);  // log(sinh d / d)
    float denom  = fmaf(2.0f * ch, g, fmaf(g, g, 1.0f));

    if (d > 1.0f) {                                      // ultra-rare exact path
        float ed = __expf(d), edi = __expf(-d);
        sh     = 0.5f * (ed - edi);
        ch     = 0.5f * (ed + edi);
        denom  = fmaf(2.0f * ch, g, fmaf(g, g, 1.0f));
        log_sc = __logf(sh * __fdividef(1.0f, d));
    }

    // include correction iff cdf_delta = 2 g sh / denom > 1e-5
    float corr  = (2.0f * g * sh > 1e-5f * denom) ? log_sc : 0.0f;
    float inner = -ls - 4.8481164f - am - __logf(denom) + corr;  // MUFU 3

    // rare edge cases (|x| > 0.999): predicated, ~0.05% of pixels
    if (x < -0.999f) {
        float pz = mid + d;
        inner = fminf(pz, 0.0f) - __logf(1.0f + __expf(-fabsf(pz)));
    } else if (x > 0.999f) {
        float q = mid - d;
        inner = -fmaxf(q, 0.0f) - __logf(1.0f + __expf(-fabsf(q)));
    }
    return inner;
}

__global__ void __launch_bounds__(TPB, 6) pixlp_kernel(
    const float* __restrict__ samples, const float* __restrict__ params,
    float* __restrict__ out)
{
    int tid = blockIdx.x * TPB + threadIdx.x;
    int p0  = tid * VEC;                 // 2 adjacent hw pixels, same batch
    int b   = p0 >> 14;
    int hw  = p0 & (HW - 1);
    const float* sp = samples + (size_t)b * 3   * HW + hw;
    const float* pp = params  + (size_t)b * 100 * HW + hw;

    float2 sv0 = ld2(sp), sv1 = ld2(sp + HW), sv2 = ld2(sp + 2 * HW);
    float xA0 = fmaf(2.0f, sv0.x, -1.0f), xB0 = fmaf(2.0f, sv0.y, -1.0f);
    float xA1 = fmaf(2.0f, sv1.x, -1.0f), xB1 = fmaf(2.0f, sv1.y, -1.0f);
    float xA2 = fmaf(2.0f, sv2.x, -1.0f), xB2 = fmaf(2.0f, sv2.y, -1.0f);

    float seA = 0.0f, seB = 0.0f;            // sum exp(logits), overflow-safe
    float mxA = -1e30f, sA = 0.0f;           // carried LSE state (per 5-group fold)
    float mxB = -1e30f, sB = 0.0f;

    #pragma unroll
    for (int gidx = 0; gidx < 2; gidx++) {
        float lpA[5], lpB[5];
        #pragma unroll
        for (int i = 0; i < 5; i++) {
            int m = gidx * 5 + i;
            float2 lg  = ld2(pp + (     m) * HW);
            float2 mu1 = ld2(pp + (10 + m) * HW);
            float2 ls1 = ld2(pp + (20 + m) * HW);
            float2 c0r = ld2(pp + (30 + m) * HW);
            float2 mu2 = ld2(pp + (40 + m) * HW);
            float2 ls2 = ld2(pp + (50 + m) * HW);
            float2 c1r = ld2(pp + (60 + m) * HW);
            float2 mu3 = ld2(pp + (70 + m) * HW);
            float2 ls3 = ld2(pp + (80 + m) * HW);
            float2 c2r = ld2(pp + (90 + m) * HW);

            seA += __expf(lg.x);
            seB += __expf(lg.y);

            // pixel A
            {
                float c0 = tanh_hw(c0r.x);
                float c1 = tanh_hw(c1r.x);
                float c2 = tanh_hw(c2r.x);
                float m2 = fmaf(c0, xA0, mu2.x);
                float m3 = fmaf(c2, xA1, fmaf(c1, xA0, mu3.x));
                lpA[i] = lg.x + chlp(xA0, mu1.x, ls1.x)
                              + chlp(xA1, m2,    ls2.x)
                              + chlp(xA2, m3,    ls3.x);
            }
            // pixel B
            {
                float c0 = tanh_hw(c0r.y);
                float c1 = tanh_hw(c1r.y);
                float c2 = tanh_hw(c2r.y);
                float m2 = fmaf(c0, xB0, mu2.y);
                float m3 = fmaf(c2, xB1, fmaf(c1, xB0, mu3.y));
                lpB[i] = lg.y + chlp(xB0, mu1.y, ls1.y)
                              + chlp(xB1, m2,    ls2.y)
                              + chlp(xB2, m3,    ls3.y);
            }
        }

        // fold group of 5 into carried (mx, s) — one extra EX2 per fold
        {
            float gm = fmaxf(fmaxf(fmaxf(lpA[0], lpA[1]), fmaxf(lpA[2], lpA[3])), lpA[4]);
            float gs = __expf(lpA[0] - gm) + __expf(lpA[1] - gm) + __expf(lpA[2] - gm)
                     + __expf(lpA[3] - gm) + __expf(lpA[4] - gm);
            if (gm > mxA) { sA = fmaf(sA, __expf(mxA - gm), gs); mxA = gm; }
            else          { sA = fmaf(gs, __expf(gm - mxA), sA); }
        }
        {
            float gm = fmaxf(fmaxf(fmaxf(lpB[0], lpB[1]), fmaxf(lpB[2], lpB[3])), lpB[4]);
            float gs = __expf(lpB[0] - gm) + __expf(lpB[1] - gm) + __expf(lpB[2] - gm)
                     + __expf(lpB[3] - gm) + __expf(lpB[4] - gm);
            if (gm > mxB) { sB = fmaf(sB, __expf(mxB - gm), gs); mxB = gm; }
            else          { sB = fmaf(gs, __expf(gm - mxB), sB); }
        }
    }

    float val = (mxA + __logf(sA) - __logf(seA))
              + (mxB + __logf(sB) - __logf(seB));

    // block reduction (fp32 within block)
    __shared__ float red[TPB];
    int t = threadIdx.x;
    red[t] = val;
    __syncthreads();
    #pragma unroll
    for (int off = TPB / 2; off > 32; off >>= 1) {
        if (t < off) red[t] += red[t + off];
        __syncthreads();
    }
    if (t < 32) {
        float w = red[t] + red[t + 32];
        #pragma unroll
        for (int off = 16; off > 0; off >>= 1)
            w += __shfl_down_sync(0xFFFFFFFFu, w, off);
        if (t == 0) red[0] = w;
    }
    __syncthreads();

    // block partial (double), last block finishes — no helper kernels
    __shared__ bool amLast;
    if (t == 0) {
        g_part[blockIdx.x] = (double)red[0];
        __threadfence();
        unsigned int done = atomicAdd(&g_count, 1u);
        amLast = (done == NBLK - 1);
    }
    __syncthreads();

    if (amLast) {
        __shared__ double redd[TPB];
        double sd = 0.0;
        for (int i = t; i < NBLK; i += TPB) sd += g_part[i];
        redd[t] = sd;
        __syncthreads();
        #pragma unroll
        for (int off = TPB / 2; off > 0; off >>= 1) {
            if (t < off) redd[t] += redd[t + off];
            __syncthreads();
        }
        if (t == 0) {
            out[0] = (float)redd[0];
            g_count = 0;                      // reset for next graph replay
        }
    }
}

extern "C" void kernel_launch(void* const* d_in, const int* in_sizes, int n_in,
                              void* d_out, int out_size)
{
    const float* samples;
    const float* params;
    if (in_sizes[0] == BATCH * 3 * HW) {
        samples = (const float*)d_in[0];
        params  = (const float*)d_in[1];
    } else {
        samples = (const float*)d_in[1];
        params  = (const float*)d_in[0];
    }
    pixlp_kernel<<<NBLK, TPB>>>(samples, params, (float*)d_out);
}

// round 13
// speedup vs baseline: 1.2763x; 1.2763x over previous
#include <cuda_runtime.h>

#define BATCH 32
#define HW    16384          // 128*128
#define NPIX  (BATCH * HW)   // 524288
#define NMIXK 10
#define TPB   256
#define NBLK  (NPIX / TPB)   // 2048

__device__ double       g_part[NBLK];
__device__ unsigned int g_count = 0;

// hardware tanh: 1 MUFU op, abs err ~5e-4
__device__ __forceinline__ float tanh_hw(float v) {
    float r;
    asm("tanh.approx.f32 %0, %1;" : "=f"(r) : "f"(v));
    return r;
}

// per-(channel, mixture) log-prob: 3 MUFU (EX2, EX2, LG2).
//
// log(cdf_delta) computed fully analytically (no underflow possible):
//   cdf_delta = sigmoid(mid+d) - sigmoid(mid-d) = 2 g sinh(d) / denom,
//     g = exp(-|mid|), denom = 1 + 2 g cosh(d) + g^2
//   log(cdf_delta) = -ls - log(255/2) - |mid| - log(denom) + log(sinh(d)/d)
// The reference's delta<=1e-5 fallback differs from this by
// log(sinh d/d) + O(g d^2) — applied unconditionally the discrepancy is
// <1e-4 in log, only on mixtures with ~e^-12 posterior weight -> final
// rel err < 1e-6. So no threshold branch, no sh polynomial at all.
__device__ __forceinline__ float chlp(float x, float mu, float lsr) {
    float ls  = fmaxf(lsr, -7.0f);
    float inv = __expf(-ls);                             // MUFU 1
    float mid = inv * (x - mu);
    float d   = inv * (1.0f / 255.0f);                   // half-width > 0
    float am  = fabsf(mid);
    float g   = __expf(-am);                             // MUFU 2

    float d2 = d * d;
    // polynomials valid for d <= 1 (typical d ~ 4e-3)
    float ch     = fmaf(d2, fmaf(d2, 4.1666667e-2f, 0.5f), 1.0f);
    float log_sc = d2 * fmaf(d2, -5.5555556e-3f, 0.16666667f);  // log(sinh d / d)

    if (d > 1.0f) {                                      // ultra-rare exact path
        float ed = __expf(d), edi = __expf(-d);
        ch     = 0.5f * (ed + edi);
        log_sc = __logf(0.5f * (ed - edi) * __fdividef(1.0f, d));
    }

    float denom = fmaf(2.0f * ch, g, fmaf(g, g, 1.0f));
    float inner = -ls - 4.8481164f - am - __logf(denom) + log_sc;  // MUFU 3

    // rare edge cases (|x| > 0.999): predicated, ~0.05% of pixels
    if (x < -0.999f) {
        float pz = mid + d;
        inner = fminf(pz, 0.0f) - __logf(1.0f + __expf(-fabsf(pz)));
    } else if (x > 0.999f) {
        float q = mid - d;
        inner = -fmaxf(q, 0.0f) - __logf(1.0f + __expf(-fabsf(q)));
    }
    return inner;
}

__global__ void __launch_bounds__(TPB, 8) pixlp_kernel(
    const float* __restrict__ samples, const float* __restrict__ params,
    float* __restrict__ out)
{
    int p  = blockIdx.x * TPB + threadIdx.x;
    int b  = p >> 14;
    int hw = p & (HW - 1);
    const float* sp = samples + (size_t)b * 3   * HW + hw;
    const float* pp = params  + (size_t)b * 100 * HW + hw;

    float x0 = fmaf(2.0f, __ldg(sp),          -1.0f);
    float x1 = fmaf(2.0f, __ldg(sp + HW),     -1.0f);
    float x2 = fmaf(2.0f, __ldg(sp + 2 * HW), -1.0f);

    float se = 0.0f;        // sum exp(logits) — |logits| small, overflow-safe
    float lp[NMIXK];        // independent per-mixture results -> full ILP

    #pragma unroll
    for (int m = 0; m < NMIXK; m++) {
        float lg  = __ldg(pp + (     m) * HW);
        float mu1 = __ldg(pp + (10 + m) * HW);
        float ls1 = __ldg(pp + (20 + m) * HW);
        float c0r = __ldg(pp + (30 + m) * HW);
        float mu2 = __ldg(pp + (40 + m) * HW);
        float ls2 = __ldg(pp + (50 + m) * HW);
        float c1r = __ldg(pp + (60 + m) * HW);
        float mu3 = __ldg(pp + (70 + m) * HW);
        float ls3 = __ldg(pp + (80 + m) * HW);
        float c2r = __ldg(pp + (90 + m) * HW);

        se += __expf(lg);

        float c0 = tanh_hw(c0r);
        float c1 = tanh_hw(c1r);
        float c2 = tanh_hw(c2r);
        float m2 = fmaf(c0, x0, mu2);
        float m3 = fmaf(c2, x1, fmaf(c1, x0, mu3));

        lp[m] = lg + chlp(x0, mu1, ls1)
                   + chlp(x1, m2,  ls2)
                   + chlp(x2, m3,  ls3);
    }

    float mx2 = lp[0];
    #pragma unroll
    for (int i = 1; i < NMIXK; i++) mx2 = fmaxf(mx2, lp[i]);
    float s2 = 0.0f;
    #pragma unroll
    for (int i = 0; i < NMIXK; i++) s2 += __expf(lp[i] - mx2);

    float val = mx2 + __logf(s2) - __logf(se);

    // block reduction (fp32 within block)
    __shared__ float red[TPB];
    int t = threadIdx.x;
    red[t] = val;
    __syncthreads();
    #pragma unroll
    for (int off = TPB / 2; off > 32; off >>= 1) {
        if (t < off) red[t] += red[t + off];
        __syncthreads();
    }
    if (t < 32) {
        float w = red[t] + red[t + 32];
        #pragma unroll
        for (int off = 16; off > 0; off >>= 1)
            w += __shfl_down_sync(0xFFFFFFFFu, w, off);
        if (t == 0) red[0] = w;
    }
    __syncthreads();

    // block partial (double), last block finishes — no helper kernels
    __shared__ bool amLast;
    if (t == 0) {
        g_part[blockIdx.x] = (double)red[0];
        __threadfence();
        unsigned int done = atomicAdd(&g_count, 1u);
        amLast = (done == NBLK - 1);
    }
    __syncthreads();

    if (amLast) {
        __shared__ double redd[TPB];
        double sd = 0.0;
        for (int i = t; i < NBLK; i += TPB) sd += g_part[i];
        redd[t] = sd;
        __syncthreads();
        #pragma unroll
        for (int off = TPB / 2; off > 0; off >>= 1) {
            if (t < off) redd[t] += redd[t + off];
            __syncthreads();
        }
        if (t == 0) {
            out[0] = (float)redd[0];
            g_count = 0;                      // reset for next graph replay
        }
    }
}

extern "C" void kernel_launch(void* const* d_in, const int* in_sizes, int n_in,
                              void* d_out, int out_size)
{
    const float* samples;
    const float* params;
    if (in_sizes[0] == BATCH * 3 * HW) {
        samples = (const float*)d_in[0];
        params  = (const float*)d_in[1];
    } else {
        samples = (const float*)d_in[1];
        params  = (const float*)d_in[0];
    }
    pixlp_kernel<<<NBLK, TPB>>>(samples, params, (float*)d_out);
}